// round 2
// baseline (speedup 1.0000x reference)
#include <cuda_runtime.h>
#include <cstdint>

#define F_DIM 1024
#define R_DIM 64
#define S_DIM 4096
#define TILE 32
#define THREADS 256
#define FCH 128
#define NCH (F_DIM / FCH)

#define PT_STRIDE 132   /* 128 + 4 : per-r bank offset = 4 -> conflict-free */
#define W_STRIDE 68     /* 64 + 4  : per-f bank offset = 4 -> conflict-free */
#define H_FLOATS (TILE * F_DIM)         /* 32768 */
#define MAT_FLOATS (FCH * W_STRIDE)     /* 8704 >= 64*132 = 8448 */
#define C_OFF (H_FLOATS + MAT_FLOATS)
#define OLD_OFF (C_OFF + TILE * R_DIM)
#define SMEM_FLOATS (OLD_OFF + TILE)
#define SMEM_BYTES (SMEM_FLOATS * 4)    /* 174208 bytes */

// ---- device scratch (no allocation allowed) ----
__device__ float g_G[R_DIM * R_DIM];
__device__ float g_M[R_DIM * R_DIM];
__device__ float g_W[F_DIM * R_DIM];    // W = P * G^-1, row-major [f][r]
__device__ float g_Pt[R_DIM * F_DIM];   // P^T, row-major [r][f]

typedef unsigned long long u64;

__device__ __forceinline__ void fma2(u64 &d, u64 a, u64 b) {
    asm("fma.rn.f32x2 %0, %1, %2, %0;" : "+l"(d) : "l"(a), "l"(b));
}
__device__ __forceinline__ float lo2(u64 v) { return __uint_as_float((unsigned)v); }
__device__ __forceinline__ float hi2(u64 v) { return __uint_as_float((unsigned)(v >> 32)); }

// ============================================================
// K1a: Gram matrix G = P^T P   (64x64 dots of length 1024)
// ============================================================
__global__ void k_gram(const float* __restrict__ probe) {
    int i = blockIdx.x >> 6, j = blockIdx.x & 63;
    float s = 0.f;
    for (int f = threadIdx.x; f < F_DIM; f += blockDim.x)
        s = fmaf(probe[f * R_DIM + i], probe[f * R_DIM + j], s);
    for (int o = 16; o; o >>= 1) s += __shfl_xor_sync(0xffffffffu, s, o);
    __shared__ float red[8];
    if ((threadIdx.x & 31) == 0) red[threadIdx.x >> 5] = s;
    __syncthreads();
    if (threadIdx.x == 0) {
        float t = 0.f;
        for (int w = 0; w < 8; w++) t += red[w];
        g_G[i * R_DIM + j] = t;
    }
}

// ============================================================
// K1b: M = G^-1 via Gauss-Jordan (G SPD + diagonally dominant,
// no pivoting needed). One block, 64 threads, one row each.
// ============================================================
__global__ void k_inv() {
    __shared__ float A[R_DIM][2 * R_DIM + 1];
    int r = threadIdx.x;
    for (int j = 0; j < R_DIM; j++) A[r][j] = g_G[r * R_DIM + j];
    for (int j = 0; j < R_DIM; j++) A[r][R_DIM + j] = (r == j) ? 1.f : 0.f;
    __syncthreads();
    for (int k = 0; k < R_DIM; k++) {
        if (r == k) {
            float inv = 1.f / A[k][k];
            for (int j = 0; j < 2 * R_DIM; j++) A[k][j] *= inv;
        }
        __syncthreads();
        if (r != k) {
            float fct = A[r][k];
            for (int j = 0; j < 2 * R_DIM; j++)
                A[r][j] = fmaf(-fct, A[k][j], A[r][j]);
        }
        __syncthreads();
    }
    for (int j = 0; j < R_DIM; j++) g_M[r * R_DIM + j] = A[r][R_DIM + j];
}

// ============================================================
// K1c: W = P * M  and  Pt = P^T
// ============================================================
__global__ void k_w(const float* __restrict__ probe) {
    __shared__ float Ms[R_DIM * R_DIM];
    for (int i = threadIdx.x; i < R_DIM * R_DIM; i += blockDim.x) Ms[i] = g_M[i];
    __syncthreads();
    int f = blockIdx.x * blockDim.x + threadIdx.x;
    float p[R_DIM];
    #pragma unroll
    for (int k = 0; k < R_DIM; k++) p[k] = probe[f * R_DIM + k];
    for (int r2 = 0; r2 < R_DIM; r2++) {
        float acc = 0.f;
        #pragma unroll
        for (int k = 0; k < R_DIM; k++) acc = fmaf(p[k], Ms[k * R_DIM + r2], acc);
        g_W[f * R_DIM + r2] = acc;
    }
    #pragma unroll
    for (int r2 = 0; r2 < R_DIM; r2++) g_Pt[r2 * F_DIM + f] = p[r2];
}

// ============================================================
// K2: main fused kernel.
// 32 rows per block, 256 threads: thread = (row = t>>3, seg = t&7).
//   phase A: c[row][r] = sum_f h[row][f] * Pt[r][f]   (f32x2 over f)
//   phase B: h[row][f] -= sum_r c[row][r] * W[f][r]   (f32x2 over r)
//   then rescale by old_norm/new_norm; s==0 rows copy input verbatim.
// ============================================================
__global__ void __launch_bounds__(THREADS, 1)
k_main(const float* __restrict__ hs, float* __restrict__ out) {
    extern __shared__ float smem[];
    float* h_s    = smem;
    float* mat_s  = smem + H_FLOATS;
    float* c_s    = smem + C_OFF;
    float* oldsq_s = smem + OLD_OFF;

    const int t = threadIdx.x;
    const int row = t >> 3;
    const int seg = t & 7;
    const long long g0 = (long long)blockIdx.x * TILE;

    // ---- load h tile, accumulate old-norm^2 per row ----
    {
        const float4* hin = (const float4*)(hs + g0 * F_DIM);
        float4* hsr = (float4*)(h_s + row * F_DIM);
        float sq = 0.f;
        #pragma unroll
        for (int k = 0; k < 32; k++) {
            float4 v = hin[row * 256 + k * 8 + seg];
            hsr[k * 8 + seg] = v;
            sq = fmaf(v.x, v.x, sq); sq = fmaf(v.y, v.y, sq);
            sq = fmaf(v.z, v.z, sq); sq = fmaf(v.w, v.w, sq);
        }
        sq += __shfl_xor_sync(0xffffffffu, sq, 1);
        sq += __shfl_xor_sync(0xffffffffu, sq, 2);
        sq += __shfl_xor_sync(0xffffffffu, sq, 4);
        if (seg == 0) oldsq_s[row] = sq;
    }
    __syncthreads();

    // ---- Phase A: coefficients c = H * P ----
    {
        u64 acc[8];
        #pragma unroll
        for (int j = 0; j < 8; j++) acc[j] = 0ull;

        for (int ch = 0; ch < NCH; ch++) {
            // stage Pt chunk [64 r][128 f] -> mat_s[r*PT_STRIDE + f]
            #pragma unroll
            for (int i = 0; i < 8; i++) {
                int idx = t + THREADS * i;
                int r2 = idx >> 5;
                int fo = (idx & 31) << 2;
                float4 v = *(const float4*)(g_Pt + r2 * F_DIM + ch * FCH + fo);
                *(float4*)(mat_s + r2 * PT_STRIDE + fo) = v;
            }
            __syncthreads();

            const float* hr = h_s + row * F_DIM + ch * FCH;
            #pragma unroll 2
            for (int f = 0; f < FCH; f += 4) {
                ulonglong2 hv = *(const ulonglong2*)(hr + f);  // broadcast (8 lanes same row)
                ulonglong2 pv[8];
                #pragma unroll
                for (int j = 0; j < 8; j++)
                    pv[j] = *(const ulonglong2*)(mat_s + (seg + 8 * j) * PT_STRIDE + f);
                #pragma unroll
                for (int j = 0; j < 8; j++) fma2(acc[j], hv.x, pv[j].x);
                #pragma unroll
                for (int j = 0; j < 8; j++) fma2(acc[j], hv.y, pv[j].y);
            }
            __syncthreads();
        }
        #pragma unroll
        for (int j = 0; j < 8; j++)
            c_s[row * R_DIM + seg + 8 * j] = lo2(acc[j]) + hi2(acc[j]);
    }
    __syncthreads();

    // ---- Phase B: h -= W * c  (in place), accumulate new-norm^2 ----
    float newsq = 0.f;
    {
        u64 creg[32];
        const u64* cr = (const u64*)(c_s + row * R_DIM);
        #pragma unroll
        for (int i = 0; i < 32; i++) creg[i] = cr[i];

        for (int ch = 0; ch < NCH; ch++) {
            // stage W chunk [128 f][64 r] -> mat_s[f*W_STRIDE + r]
            #pragma unroll
            for (int i = 0; i < 8; i++) {
                int idx = t + THREADS * i;
                int j = idx >> 4;
                int ro = (idx & 15) << 2;
                float4 v = *(const float4*)(g_W + (long long)(ch * FCH + j) * R_DIM + ro);
                *(float4*)(mat_s + j * W_STRIDE + ro) = v;
            }
            __syncthreads();

            #pragma unroll 2
            for (int i = 0; i < 16; i++) {
                int j = i * 8 + seg;
                const ulonglong2* wr = (const ulonglong2*)(mat_s + j * W_STRIDE);
                u64 a0 = 0ull, a1 = 0ull, a2 = 0ull, a3 = 0ull;
                #pragma unroll
                for (int q = 0; q < 16; q += 2) {
                    ulonglong2 w0 = wr[q];
                    ulonglong2 w1 = wr[q + 1];
                    fma2(a0, creg[2 * q],     w0.x);
                    fma2(a1, creg[2 * q + 1], w0.y);
                    fma2(a2, creg[2 * q + 2], w1.x);
                    fma2(a3, creg[2 * q + 3], w1.y);
                }
                float proj = (lo2(a0) + hi2(a0)) + (lo2(a1) + hi2(a1))
                           + (lo2(a2) + hi2(a2)) + (lo2(a3) + hi2(a3));
                int fi = row * F_DIM + ch * FCH + j;
                float o = h_s[fi] - proj;
                h_s[fi] = o;
                newsq = fmaf(o, o, newsq);
            }
            __syncthreads();
        }
    }

    // ---- per-row scale = old_norm / new_norm ----
    newsq += __shfl_xor_sync(0xffffffffu, newsq, 1);
    newsq += __shfl_xor_sync(0xffffffffu, newsq, 2);
    newsq += __shfl_xor_sync(0xffffffffu, newsq, 4);
    float scale = sqrtf(oldsq_s[row] / newsq);

    // ---- store (s==0 rows: copy original input) ----
    {
        long long grow = g0 + row;
        bool first = ((grow & (S_DIM - 1)) == 0);
        float4* orow = (float4*)(out + grow * F_DIM);
        if (!first) {
            const float4* hsr = (const float4*)(h_s + row * F_DIM);
            #pragma unroll
            for (int k = 0; k < 32; k++) {
                float4 v = hsr[k * 8 + seg];
                v.x *= scale; v.y *= scale; v.z *= scale; v.w *= scale;
                orow[k * 8 + seg] = v;
            }
        } else {
            const float4* irow = (const float4*)(hs + grow * F_DIM);
            #pragma unroll
            for (int k = 0; k < 32; k++) orow[k * 8 + seg] = irow[k * 8 + seg];
        }
    }
}

extern "C" void kernel_launch(void* const* d_in, const int* in_sizes, int n_in,
                              void* d_out, int out_size) {
    const float* hs = (const float*)d_in[0];
    const float* probe = (const float*)d_in[1];
    float* out = (float*)d_out;

    // precompute projector factors (tiny)
    k_gram<<<R_DIM * R_DIM, 256>>>(probe);
    k_inv<<<1, R_DIM>>>();
    k_w<<<F_DIM / 256, 256>>>(probe);

    // main fused pass
    cudaFuncSetAttribute(k_main, cudaFuncAttributeMaxDynamicSharedMemorySize, SMEM_BYTES);
    int rows = in_sizes[0] / F_DIM;        // 32768
    k_main<<<rows / TILE, THREADS, SMEM_BYTES>>>(hs, out);
}

// round 5
// speedup vs baseline: 2.5477x; 2.5477x over previous
#include <cuda_runtime.h>
#include <cstdint>

#define FD 1024
#define RD 64
#define MT 128
#define NCH 16          // GEMM1 chunks of 64 cols
#define WST 68          // A smem row stride in words (32 hi + 32 lo + 4 pad)

// ---------------- device scratch ----------------
__device__ float g_G[RD * RD];
__device__ float g_Minv[RD * RD];
__device__ float g_W[FD * RD];          // W = P * Minv, [f][r]
__device__ uint4 g_PP[64 * 8 * 32];     // GEMM1 B frags: [kstep][ntile][lane]
__device__ uint4 g_WP[128 * 4 * 32];    // GEMM2 B frags: [ntile][kstep][lane]
__device__ uint4 g_MP[8 * 4 * 32];      // d3 B frags (Minv)

// ---------------- helpers ----------------
// pack two f32 -> bf16x2 (x in low half), plus residual pack
__device__ __forceinline__ void split2(float x, float y, uint32_t& hi, uint32_t& lo) {
    asm("cvt.rn.bf16x2.f32 %0, %1, %2;" : "=r"(hi) : "f"(y), "f"(x));
    float xr = x - __uint_as_float(hi << 16);
    float yr = y - __uint_as_float(hi & 0xffff0000u);
    asm("cvt.rn.bf16x2.f32 %0, %1, %2;" : "=r"(lo) : "f"(yr), "f"(xr));
}

__device__ __forceinline__ void mma_bf16(float* d,
    uint32_t a0, uint32_t a1, uint32_t a2, uint32_t a3,
    uint32_t b0, uint32_t b1) {
    asm volatile("mma.sync.aligned.m16n8k16.row.col.f32.bf16.bf16.f32 "
        "{%0,%1,%2,%3}, {%4,%5,%6,%7}, {%8,%9}, {%0,%1,%2,%3};"
        : "+f"(d[0]), "+f"(d[1]), "+f"(d[2]), "+f"(d[3])
        : "r"(a0), "r"(a1), "r"(a2), "r"(a3), "r"(b0), "r"(b1));
}

// ---------------- prep kernels ----------------
__global__ void k_zero() {
    for (int i = threadIdx.x; i < RD * RD; i += 256) g_G[i] = 0.f;
}

__global__ void k_gram(const float* __restrict__ probe) {
    __shared__ float Ps[128][68];    // stride 68 floats = 272 B (16B multiple!)
    int c = blockIdx.x, t = threadIdx.x;
    #pragma unroll
    for (int i = 0; i < 8; i++) {
        int idx = t + 256 * i;
        int fl = idx >> 4, r4 = (idx & 15) << 2;
        float4 v = *(const float4*)(probe + (c * 128 + fl) * 64 + r4);
        *(float4*)(&Ps[fl][r4]) = v;
    }
    __syncthreads();
    int ti = (t >> 4) << 2, tj = (t & 15) << 2;
    float acc[4][4];
    #pragma unroll
    for (int a = 0; a < 4; a++)
        #pragma unroll
        for (int b = 0; b < 4; b++) acc[a][b] = 0.f;
    for (int k = 0; k < 128; k++) {
        float av[4], bv[4];
        #pragma unroll
        for (int a = 0; a < 4; a++) av[a] = Ps[k][ti + a];
        #pragma unroll
        for (int b = 0; b < 4; b++) bv[b] = Ps[k][tj + b];
        #pragma unroll
        for (int a = 0; a < 4; a++)
            #pragma unroll
            for (int b = 0; b < 4; b++) acc[a][b] = fmaf(av[a], bv[b], acc[a][b]);
    }
    #pragma unroll
    for (int a = 0; a < 4; a++)
        #pragma unroll
        for (int b = 0; b < 4; b++)
            atomicAdd(&g_G[(ti + a) * 64 + tj + b], acc[a][b]);
}

__global__ void k_inv() {
    __shared__ float A[64][129];
    int r = threadIdx.x;
    for (int j = 0; j < 64; j++) A[r][j] = g_G[r * 64 + j];
    for (int j = 0; j < 64; j++) A[r][64 + j] = (r == j) ? 1.f : 0.f;
    __syncthreads();
    for (int k = 0; k < 64; k++) {
        if (r == k) {
            float inv = 1.f / A[k][k];
            for (int j = 0; j < 128; j++) A[k][j] *= inv;
        }
        __syncthreads();
        if (r != k) {
            float f = A[r][k];
            for (int j = 0; j < 128; j++) A[r][j] = fmaf(-f, A[k][j], A[r][j]);
        }
        __syncthreads();
    }
    for (int j = 0; j < 64; j++) g_Minv[r * 64 + j] = A[r][64 + j];
}

__global__ void k_w(const float* __restrict__ probe) {
    __shared__ float Ms[64 * 64];
    for (int i = threadIdx.x; i < 64 * 64; i += 256) Ms[i] = g_Minv[i];
    __syncthreads();
    int f = blockIdx.x * 256 + threadIdx.x;
    float p[64];
    #pragma unroll
    for (int k = 0; k < 64; k++) p[k] = probe[f * 64 + k];
    for (int r = 0; r < 64; r++) {
        float acc = 0.f;
        #pragma unroll
        for (int k = 0; k < 64; k++) acc = fmaf(p[k], Ms[k * 64 + r], acc);
        g_W[f * 64 + r] = acc;
    }
}

__global__ void k_pack_p(const float* __restrict__ probe) {
    int id = blockIdx.x * 256 + threadIdx.x;           // 0..16383
    int lane = id & 31, g = lane >> 2, tq = lane & 3;
    int kk = id >> 8, j = (id >> 5) & 7;
    int n = 8 * j + g, k0 = 16 * kk + 2 * tq;
    float p00 = probe[(k0) * 64 + n], p01 = probe[(k0 + 1) * 64 + n];
    float p10 = probe[(k0 + 8) * 64 + n], p11 = probe[(k0 + 9) * 64 + n];
    uint32_t h0, l0, h1, l1;
    split2(p00, p01, h0, l0);
    split2(p10, p11, h1, l1);
    g_PP[id] = make_uint4(h0, h1, l0, l1);
}

__global__ void k_pack_w() {
    int id = blockIdx.x * 256 + threadIdx.x;           // 0..16383
    int lane = id & 31, g = lane >> 2, tq = lane & 3;
    int jj = id >> 7, kk = (id >> 5) & 3;
    int f = 8 * jj + g, r0 = 16 * kk + 2 * tq;
    float w00 = g_W[f * 64 + r0], w01 = g_W[f * 64 + r0 + 1];
    float w10 = g_W[f * 64 + r0 + 8], w11 = g_W[f * 64 + r0 + 9];
    uint32_t h0, l0, h1, l1;
    split2(w00, w01, h0, l0);
    split2(w10, w11, h1, l1);
    g_WP[id] = make_uint4(h0, h1, l0, l1);
}

__global__ void k_pack_m() {
    int id = blockIdx.x * 256 + threadIdx.x;           // 0..1023
    int lane = id & 31, g = lane >> 2, tq = lane & 3;
    int j = id >> 7, kk = (id >> 5) & 3;
    int n = 8 * j + g, k0 = 16 * kk + 2 * tq;
    float m00 = g_Minv[(k0) * 64 + n], m01 = g_Minv[(k0 + 1) * 64 + n];
    float m10 = g_Minv[(k0 + 8) * 64 + n], m11 = g_Minv[(k0 + 9) * 64 + n];
    uint32_t h0, l0, h1, l1;
    split2(m00, m01, h0, l0);
    split2(m10, m11, h1, l1);
    g_MP[id] = make_uint4(h0, h1, l0, l1);
}

// ---------------- main kernel ----------------
// smem words: A bufs [0..17408), B1 frags [17408..25600), osq [25600..25728)
#define SMEM_WORDS 25728
#define SMEM_BYTES (SMEM_WORDS * 4)

__global__ void __launch_bounds__(256, 1)
k_main(const float* __restrict__ hs, float* __restrict__ out) {
    extern __shared__ uint32_t smw[];
    uint4* B1s = (uint4*)(smw + 17408);
    uint4* W2s = (uint4*)smw;            // phase-2 reuse of A region
    float* osq_s = (float*)(smw + 25600);

    const int t = threadIdx.x;
    const int wg = t >> 5, lane = t & 31, g = lane >> 2, tq = lane & 3;
    const int rr = t >> 4, cc = t & 15;
    const size_t g0 = (size_t)blockIdx.x * MT;

    float acc1[8][4];
    #pragma unroll
    for (int j = 0; j < 8; j++)
        #pragma unroll
        for (int q = 0; q < 4; q++) acc1[j][q] = 0.f;
    float sq[8];
    #pragma unroll
    for (int i = 0; i < 8; i++) sq[i] = 0.f;

    float4 hv[8];
    uint4 bv4[4];

    // ---- stage chunk 0 ----
    #pragma unroll
    for (int i = 0; i < 8; i++)
        hv[i] = *(const float4*)(hs + (g0 + rr + 16 * i) * FD + cc * 4);
    #pragma unroll
    for (int q = 0; q < 4; q++) bv4[q] = g_PP[t + 256 * q];
    #pragma unroll
    for (int i = 0; i < 8; i++) {
        float4 v = hv[i];
        sq[i] = fmaf(v.x, v.x, sq[i]); sq[i] = fmaf(v.y, v.y, sq[i]);
        sq[i] = fmaf(v.z, v.z, sq[i]); sq[i] = fmaf(v.w, v.w, sq[i]);
        uint32_t h0, l0, h1, l1;
        split2(v.x, v.y, h0, l0); split2(v.z, v.w, h1, l1);
        int base = (rr + 16 * i) * WST + cc * 2;
        *(uint2*)(smw + base) = make_uint2(h0, h1);
        *(uint2*)(smw + base + 32) = make_uint2(l0, l1);
    }
    #pragma unroll
    for (int q = 0; q < 4; q++) B1s[t + 256 * q] = bv4[q];

    // ======== GEMM1: acc1 = H * P, K = 1024 ========
    for (int ch = 0; ch < NCH; ch++) {
        __syncthreads();
        const int buf = ch & 1;
        if (ch + 1 < NCH) {
            #pragma unroll
            for (int i = 0; i < 8; i++)
                hv[i] = *(const float4*)(hs + (g0 + rr + 16 * i) * FD + (ch + 1) * 64 + cc * 4);
            #pragma unroll
            for (int q = 0; q < 4; q++) bv4[q] = g_PP[(ch + 1) * 1024 + t + 256 * q];
        }
        // mma on chunk ch
        const int abase = buf * 8704;
        #pragma unroll
        for (int kk = 0; kk < 4; kk++) {
            int r0w = abase + (16 * wg + g) * WST + 8 * kk;
            int r1w = r0w + 8 * WST;
            uint32_t ah0 = smw[r0w + tq],      ah1 = smw[r1w + tq];
            uint32_t ah2 = smw[r0w + 4 + tq],  ah3 = smw[r1w + 4 + tq];
            uint32_t al0 = smw[r0w + 32 + tq], al1 = smw[r1w + 32 + tq];
            uint32_t al2 = smw[r0w + 36 + tq], al3 = smw[r1w + 36 + tq];
            #pragma unroll
            for (int j = 0; j < 8; j++) {
                uint4 bb = B1s[buf * 1024 + (kk * 8 + j) * 32 + lane];
                mma_bf16(acc1[j], ah0, ah1, ah2, ah3, bb.x, bb.y);
                mma_bf16(acc1[j], ah0, ah1, ah2, ah3, bb.z, bb.w);
                mma_bf16(acc1[j], al0, al1, al2, al3, bb.x, bb.y);
            }
        }
        if (ch + 1 < NCH) {
            const int nbase = ((ch + 1) & 1) * 8704;
            #pragma unroll
            for (int i = 0; i < 8; i++) {
                float4 v = hv[i];
                sq[i] = fmaf(v.x, v.x, sq[i]); sq[i] = fmaf(v.y, v.y, sq[i]);
                sq[i] = fmaf(v.z, v.z, sq[i]); sq[i] = fmaf(v.w, v.w, sq[i]);
                uint32_t h0, l0, h1, l1;
                split2(v.x, v.y, h0, l0); split2(v.z, v.w, h1, l1);
                int base = nbase + (rr + 16 * i) * WST + cc * 2;
                *(uint2*)(smw + base) = make_uint2(h0, h1);
                *(uint2*)(smw + base + 32) = make_uint2(l0, l1);
            }
            #pragma unroll
            for (int q = 0; q < 4; q++)
                B1s[((ch + 1) & 1) * 1024 + t + 256 * q] = bv4[q];
        }
    }

    // ---- old-norm^2 per row ----
    #pragma unroll
    for (int i = 0; i < 8; i++) {
        float s = sq[i];
        s += __shfl_xor_sync(~0u, s, 1); s += __shfl_xor_sync(~0u, s, 2);
        s += __shfl_xor_sync(~0u, s, 4); s += __shfl_xor_sync(~0u, s, 8);
        sq[i] = s;
    }
    if ((t & 15) == 0) {
        int m = t >> 4;
        #pragma unroll
        for (int i = 0; i < 8; i++) osq_s[m + 16 * i] = sq[i];
    }
    __syncthreads();

    // prefetch WtP chunk 0
    uint4 wv[8];
    #pragma unroll
    for (int q = 0; q < 8; q++) wv[q] = g_WP[t + 256 * q];

    // ---- repack acc1 (C frags) into GEMM2 A frags ----
    uint32_t a2h[4][4], a2l[4][4];
    #pragma unroll
    for (int kk = 0; kk < 4; kk++) {
        split2(acc1[2 * kk][0],     acc1[2 * kk][1],     a2h[kk][0], a2l[kk][0]);
        split2(acc1[2 * kk][2],     acc1[2 * kk][3],     a2h[kk][1], a2l[kk][1]);
        split2(acc1[2 * kk + 1][0], acc1[2 * kk + 1][1], a2h[kk][2], a2l[kk][2]);
        split2(acc1[2 * kk + 1][2], acc1[2 * kk + 1][3], a2h[kk][3], a2l[kk][3]);
    }

    // ---- d3 = b * Minv; dot = b . d3 ; scales ----
    float accd[8][4];
    #pragma unroll
    for (int j = 0; j < 8; j++)
        #pragma unroll
        for (int q = 0; q < 4; q++) accd[j][q] = 0.f;
    #pragma unroll
    for (int kk = 0; kk < 4; kk++)
        #pragma unroll
        for (int j = 0; j < 8; j++) {
            uint4 bb = g_MP[(j * 4 + kk) * 32 + lane];
            mma_bf16(accd[j], a2h[kk][0], a2h[kk][1], a2h[kk][2], a2h[kk][3], bb.x, bb.y);
            mma_bf16(accd[j], a2h[kk][0], a2h[kk][1], a2h[kk][2], a2h[kk][3], bb.z, bb.w);
            mma_bf16(accd[j], a2l[kk][0], a2l[kk][1], a2l[kk][2], a2l[kk][3], bb.x, bb.y);
        }
    float dA = 0.f, dB = 0.f;
    #pragma unroll
    for (int j = 0; j < 8; j++) {
        dA = fmaf(acc1[j][0], accd[j][0], dA); dA = fmaf(acc1[j][1], accd[j][1], dA);
        dB = fmaf(acc1[j][2], accd[j][2], dB); dB = fmaf(acc1[j][3], accd[j][3], dB);
    }
    dA += __shfl_xor_sync(~0u, dA, 1); dA += __shfl_xor_sync(~0u, dA, 2);
    dB += __shfl_xor_sync(~0u, dB, 1); dB += __shfl_xor_sync(~0u, dB, 2);
    float oA = osq_s[16 * wg + g], oB = osq_s[16 * wg + g + 8];
    float scA = sqrtf(oA / fmaxf(oA - dA, oA * 1e-12f));
    float scB = sqrtf(oB / fmaxf(oB - dB, oB * 1e-12f));

    // STS WtP chunk 0
    #pragma unroll
    for (int q = 0; q < 8; q++) W2s[t + 256 * q] = wv[q];

    // ======== GEMM2 + fused epilogue: out = (H - b*Wt) * scale ========
    const size_t rowA = g0 + 16 * wg + g, rowB = rowA + 8;
    const float* hA = hs + rowA * FD;
    const float* hB = hs + rowB * FD;
    float* pA = out + rowA * FD;
    float* pB = out + rowB * FD;
    const bool fA = ((rowA & 4095) == 0);
    const bool fB = ((rowB & 4095) == 0);

    for (int nc = 0; nc < 8; nc++) {
        __syncthreads();
        const int buf = nc & 1;
        if (nc + 1 < 8) {
            #pragma unroll
            for (int q = 0; q < 8; q++) wv[q] = g_WP[(nc + 1) * 2048 + t + 256 * q];
        }
        float acc2[16][4];
        #pragma unroll
        for (int jl = 0; jl < 16; jl++)
            #pragma unroll
            for (int q = 0; q < 4; q++) acc2[jl][q] = 0.f;
        #pragma unroll
        for (int kk = 0; kk < 4; kk++)
            #pragma unroll
            for (int jl = 0; jl < 16; jl++) {
                uint4 bb = W2s[buf * 2048 + (jl * 4 + kk) * 32 + lane];
                mma_bf16(acc2[jl], a2h[kk][0], a2h[kk][1], a2h[kk][2], a2h[kk][3], bb.x, bb.y);
                mma_bf16(acc2[jl], a2h[kk][0], a2h[kk][1], a2h[kk][2], a2h[kk][3], bb.z, bb.w);
                mma_bf16(acc2[jl], a2l[kk][0], a2l[kk][1], a2l[kk][2], a2l[kk][3], bb.x, bb.y);
            }
        #pragma unroll
        for (int jl = 0; jl < 16; jl++) {
            int col = nc * 128 + jl * 8 + 2 * tq;
            float2 h0 = *(const float2*)(hA + col);
            float2 h1 = *(const float2*)(hB + col);
            float2 o0, o1;
            o0.x = fA ? h0.x : (h0.x - acc2[jl][0]) * scA;
            o0.y = fA ? h0.y : (h0.y - acc2[jl][1]) * scA;
            o1.x = fB ? h1.x : (h1.x - acc2[jl][2]) * scB;
            o1.y = fB ? h1.y : (h1.y - acc2[jl][3]) * scB;
            *(float2*)(pA + col) = o0;
            *(float2*)(pB + col) = o1;
        }
        if (nc + 1 < 8) {
            #pragma unroll
            for (int q = 0; q < 8; q++)
                W2s[((nc + 1) & 1) * 2048 + t + 256 * q] = wv[q];
        }
    }
}

extern "C" void kernel_launch(void* const* d_in, const int* in_sizes, int n_in,
                              void* d_out, int out_size) {
    const float* hs = (const float*)d_in[0];
    const float* probe = (const float*)d_in[1];
    float* out = (float*)d_out;

    k_zero<<<1, 256>>>();
    k_gram<<<8, 256>>>(probe);
    k_inv<<<1, 64>>>();
    k_w<<<4, 256>>>(probe);
    k_pack_p<<<64, 256>>>(probe);
    k_pack_w<<<64, 256>>>();
    k_pack_m<<<4, 256>>>();

    cudaFuncSetAttribute(k_main, cudaFuncAttributeMaxDynamicSharedMemorySize, SMEM_BYTES);
    int rows = in_sizes[0] / FD;            // 32768
    k_main<<<rows / MT, 256, SMEM_BYTES>>>(hs, out);
}

// round 6
// speedup vs baseline: 2.5807x; 1.0129x over previous
#include <cuda_runtime.h>
#include <cstdint>

#define FD 1024
#define RD 64
#define MT 128
#define NCH 16          // GEMM1 chunks of 64 cols
#define WST 68          // A smem row stride in words (32 hi + 32 lo + 4 pad)

// ---------------- device scratch ----------------
__device__ float g_G[RD * RD];
__device__ float g_Minv[RD * RD];
__device__ float g_W[FD * RD];          // W = P * Minv, [f][r]
__device__ uint4 g_PP[64 * 8 * 32];     // GEMM1 B frags: [kstep][ntile][lane]
__device__ uint4 g_WP[128 * 4 * 32];    // GEMM2 B frags: [ntile][kstep][lane]
__device__ uint4 g_MP[8 * 4 * 32];      // d3 B frags (Minv)

// ---------------- helpers ----------------
__device__ __forceinline__ void split2(float x, float y, uint32_t& hi, uint32_t& lo) {
    asm("cvt.rn.bf16x2.f32 %0, %1, %2;" : "=r"(hi) : "f"(y), "f"(x));
    float xr = x - __uint_as_float(hi << 16);
    float yr = y - __uint_as_float(hi & 0xffff0000u);
    asm("cvt.rn.bf16x2.f32 %0, %1, %2;" : "=r"(lo) : "f"(yr), "f"(xr));
}

__device__ __forceinline__ void mma_bf16(float* d,
    uint32_t a0, uint32_t a1, uint32_t a2, uint32_t a3,
    uint32_t b0, uint32_t b1) {
    asm volatile("mma.sync.aligned.m16n8k16.row.col.f32.bf16.bf16.f32 "
        "{%0,%1,%2,%3}, {%4,%5,%6,%7}, {%8,%9}, {%0,%1,%2,%3};"
        : "+f"(d[0]), "+f"(d[1]), "+f"(d[2]), "+f"(d[3])
        : "r"(a0), "r"(a1), "r"(a2), "r"(a3), "r"(b0), "r"(b1));
}

// ---------------- prep kernels ----------------
__global__ void k_zero() {
    for (int i = threadIdx.x; i < RD * RD; i += 256) g_G[i] = 0.f;
}

__global__ void k_gram(const float* __restrict__ probe) {
    __shared__ float Ps[128][68];
    int c = blockIdx.x, t = threadIdx.x;
    #pragma unroll
    for (int i = 0; i < 8; i++) {
        int idx = t + 256 * i;
        int fl = idx >> 4, r4 = (idx & 15) << 2;
        float4 v = *(const float4*)(probe + (c * 128 + fl) * 64 + r4);
        *(float4*)(&Ps[fl][r4]) = v;
    }
    __syncthreads();
    int ti = (t >> 4) << 2, tj = (t & 15) << 2;
    float acc[4][4];
    #pragma unroll
    for (int a = 0; a < 4; a++)
        #pragma unroll
        for (int b = 0; b < 4; b++) acc[a][b] = 0.f;
    for (int k = 0; k < 128; k++) {
        float av[4], bv[4];
        #pragma unroll
        for (int a = 0; a < 4; a++) av[a] = Ps[k][ti + a];
        #pragma unroll
        for (int b = 0; b < 4; b++) bv[b] = Ps[k][tj + b];
        #pragma unroll
        for (int a = 0; a < 4; a++)
            #pragma unroll
            for (int b = 0; b < 4; b++) acc[a][b] = fmaf(av[a], bv[b], acc[a][b]);
    }
    #pragma unroll
    for (int a = 0; a < 4; a++)
        #pragma unroll
        for (int b = 0; b < 4; b++)
            atomicAdd(&g_G[(ti + a) * 64 + tj + b], acc[a][b]);
}

__global__ void k_inv() {
    __shared__ float A[64][129];
    int r = threadIdx.x;
    for (int j = 0; j < 64; j++) A[r][j] = g_G[r * 64 + j];
    for (int j = 0; j < 64; j++) A[r][64 + j] = (r == j) ? 1.f : 0.f;
    __syncthreads();
    for (int k = 0; k < 64; k++) {
        if (r == k) {
            float inv = 1.f / A[k][k];
            for (int j = 0; j < 128; j++) A[k][j] *= inv;
        }
        __syncthreads();
        if (r != k) {
            float f = A[r][k];
            for (int j = 0; j < 128; j++) A[r][j] = fmaf(-f, A[k][j], A[r][j]);
        }
        __syncthreads();
    }
    for (int j = 0; j < 64; j++) g_Minv[r * 64 + j] = A[r][64 + j];
}

// parallel W = P * Minv: one thread per (f, r); grid 256 x 256 threads
__global__ void k_w(const float* __restrict__ probe) {
    __shared__ float Ms[64 * 64];
    __shared__ float Ps[4][64];
    int t = threadIdx.x;
    for (int i = t; i < 4096; i += 256) Ms[i] = g_Minv[i];
    {
        int fl = t >> 6, k = t & 63;
        Ps[fl][k] = probe[(blockIdx.x * 4 + fl) * 64 + k];
    }
    __syncthreads();
    int fl = t >> 6, r = t & 63;
    float acc = 0.f;
    #pragma unroll 16
    for (int k = 0; k < 64; k++) acc = fmaf(Ps[fl][k], Ms[k * 64 + r], acc);
    g_W[(blockIdx.x * 4 + fl) * 64 + r] = acc;
}

__global__ void k_pack_p(const float* __restrict__ probe) {
    int id = blockIdx.x * 256 + threadIdx.x;
    int lane = id & 31, g = lane >> 2, tq = lane & 3;
    int kk = id >> 8, j = (id >> 5) & 7;
    int n = 8 * j + g, k0 = 16 * kk + 2 * tq;
    float p00 = probe[(k0) * 64 + n], p01 = probe[(k0 + 1) * 64 + n];
    float p10 = probe[(k0 + 8) * 64 + n], p11 = probe[(k0 + 9) * 64 + n];
    uint32_t h0, l0, h1, l1;
    split2(p00, p01, h0, l0);
    split2(p10, p11, h1, l1);
    g_PP[id] = make_uint4(h0, h1, l0, l1);
}

__global__ void k_pack_w() {
    int id = blockIdx.x * 256 + threadIdx.x;
    int lane = id & 31, g = lane >> 2, tq = lane & 3;
    int jj = id >> 7, kk = (id >> 5) & 3;
    int f = 8 * jj + g, r0 = 16 * kk + 2 * tq;
    float w00 = g_W[f * 64 + r0], w01 = g_W[f * 64 + r0 + 1];
    float w10 = g_W[f * 64 + r0 + 8], w11 = g_W[f * 64 + r0 + 9];
    uint32_t h0, l0, h1, l1;
    split2(w00, w01, h0, l0);
    split2(w10, w11, h1, l1);
    g_WP[id] = make_uint4(h0, h1, l0, l1);
}

__global__ void k_pack_m() {
    int id = blockIdx.x * 256 + threadIdx.x;
    int lane = id & 31, g = lane >> 2, tq = lane & 3;
    int j = id >> 7, kk = (id >> 5) & 3;
    int n = 8 * j + g, k0 = 16 * kk + 2 * tq;
    float m00 = g_Minv[(k0) * 64 + n], m01 = g_Minv[(k0 + 1) * 64 + n];
    float m10 = g_Minv[(k0 + 8) * 64 + n], m11 = g_Minv[(k0 + 9) * 64 + n];
    uint32_t h0, l0, h1, l1;
    split2(m00, m01, h0, l0);
    split2(m10, m11, h1, l1);
    g_MP[id] = make_uint4(h0, h1, l0, l1);
}

// ---------------- main kernel ----------------
// smem words: A bufs [0..17408), B1 frags [17408..25600), osq [25600..25728)
#define SMEM_WORDS 25728
#define SMEM_BYTES (SMEM_WORDS * 4)

__global__ void __launch_bounds__(256, 2)
k_main(const float* __restrict__ hs, float* __restrict__ out) {
    extern __shared__ uint32_t smw[];
    uint4* B1s = (uint4*)(smw + 17408);
    uint4* W2s = (uint4*)smw;            // phase-2 reuse of A region
    float* osq_s = (float*)(smw + 25600);

    const int t = threadIdx.x;
    const int wg = t >> 5, lane = t & 31, g = lane >> 2, tq = lane & 3;
    const int rr = t >> 4, cc = t & 15;
    const size_t g0 = (size_t)blockIdx.x * MT;

    float acc1[8][4];
    #pragma unroll
    for (int j = 0; j < 8; j++)
        #pragma unroll
        for (int q = 0; q < 4; q++) acc1[j][q] = 0.f;
    float sq[8];
    #pragma unroll
    for (int i = 0; i < 8; i++) sq[i] = 0.f;

    float4 hv[8];
    uint4 bv4[4];

    // ---- stage chunk 0 ----
    #pragma unroll
    for (int i = 0; i < 8; i++)
        hv[i] = *(const float4*)(hs + (g0 + rr + 16 * i) * FD + cc * 4);
    #pragma unroll
    for (int q = 0; q < 4; q++) bv4[q] = g_PP[t + 256 * q];
    #pragma unroll
    for (int i = 0; i < 8; i++) {
        float4 v = hv[i];
        sq[i] = fmaf(v.x, v.x, sq[i]); sq[i] = fmaf(v.y, v.y, sq[i]);
        sq[i] = fmaf(v.z, v.z, sq[i]); sq[i] = fmaf(v.w, v.w, sq[i]);
        uint32_t h0, l0, h1, l1;
        split2(v.x, v.y, h0, l0); split2(v.z, v.w, h1, l1);
        int base = (rr + 16 * i) * WST + cc * 2;
        *(uint2*)(smw + base) = make_uint2(h0, h1);
        *(uint2*)(smw + base + 32) = make_uint2(l0, l1);
    }
    #pragma unroll
    for (int q = 0; q < 4; q++) B1s[t + 256 * q] = bv4[q];

    // ======== GEMM1: acc1 = H * P, K = 1024 ========
    for (int ch = 0; ch < NCH; ch++) {
        __syncthreads();
        const int buf = ch & 1;
        if (ch + 1 < NCH) {
            #pragma unroll
            for (int i = 0; i < 8; i++)
                hv[i] = *(const float4*)(hs + (g0 + rr + 16 * i) * FD + (ch + 1) * 64 + cc * 4);
            #pragma unroll
            for (int q = 0; q < 4; q++) bv4[q] = g_PP[(ch + 1) * 1024 + t + 256 * q];
        }
        const int abase = buf * 8704;
        #pragma unroll
        for (int kk = 0; kk < 4; kk++) {
            int r0w = abase + (16 * wg + g) * WST + 8 * kk;
            int r1w = r0w + 8 * WST;
            uint32_t ah0 = smw[r0w + tq],      ah1 = smw[r1w + tq];
            uint32_t ah2 = smw[r0w + 4 + tq],  ah3 = smw[r1w + 4 + tq];
            uint32_t al0 = smw[r0w + 32 + tq], al1 = smw[r1w + 32 + tq];
            uint32_t al2 = smw[r0w + 36 + tq], al3 = smw[r1w + 36 + tq];
            #pragma unroll
            for (int j = 0; j < 8; j++) {
                uint4 bb = B1s[buf * 1024 + (kk * 8 + j) * 32 + lane];
                mma_bf16(acc1[j], ah0, ah1, ah2, ah3, bb.x, bb.y);
                mma_bf16(acc1[j], ah0, ah1, ah2, ah3, bb.z, bb.w);
                mma_bf16(acc1[j], al0, al1, al2, al3, bb.x, bb.y);
            }
        }
        if (ch + 1 < NCH) {
            const int nbase = ((ch + 1) & 1) * 8704;
            #pragma unroll
            for (int i = 0; i < 8; i++) {
                float4 v = hv[i];
                sq[i] = fmaf(v.x, v.x, sq[i]); sq[i] = fmaf(v.y, v.y, sq[i]);
                sq[i] = fmaf(v.z, v.z, sq[i]); sq[i] = fmaf(v.w, v.w, sq[i]);
                uint32_t h0, l0, h1, l1;
                split2(v.x, v.y, h0, l0); split2(v.z, v.w, h1, l1);
                int base = nbase + (rr + 16 * i) * WST + cc * 2;
                *(uint2*)(smw + base) = make_uint2(h0, h1);
                *(uint2*)(smw + base + 32) = make_uint2(l0, l1);
            }
            #pragma unroll
            for (int q = 0; q < 4; q++)
                B1s[((ch + 1) & 1) * 1024 + t + 256 * q] = bv4[q];
        }
    }

    // ---- old-norm^2 per row ----
    #pragma unroll
    for (int i = 0; i < 8; i++) {
        float s = sq[i];
        s += __shfl_xor_sync(~0u, s, 1); s += __shfl_xor_sync(~0u, s, 2);
        s += __shfl_xor_sync(~0u, s, 4); s += __shfl_xor_sync(~0u, s, 8);
        sq[i] = s;
    }
    if ((t & 15) == 0) {
        int m = t >> 4;
        #pragma unroll
        for (int i = 0; i < 8; i++) osq_s[m + 16 * i] = sq[i];
    }
    __syncthreads();

    // prefetch WtP chunk 0
    uint4 wv[8];
    #pragma unroll
    for (int q = 0; q < 8; q++) wv[q] = g_WP[t + 256 * q];

    // ---- repack acc1 (C frags) into GEMM2 A frags ----
    uint32_t a2h[4][4], a2l[4][4];
    #pragma unroll
    for (int kk = 0; kk < 4; kk++) {
        split2(acc1[2 * kk][0],     acc1[2 * kk][1],     a2h[kk][0], a2l[kk][0]);
        split2(acc1[2 * kk][2],     acc1[2 * kk][3],     a2h[kk][1], a2l[kk][1]);
        split2(acc1[2 * kk + 1][0], acc1[2 * kk + 1][1], a2h[kk][2], a2l[kk][2]);
        split2(acc1[2 * kk + 1][2], acc1[2 * kk + 1][3], a2h[kk][3], a2l[kk][3]);
    }

    // ---- d3 = b * Minv; dot = b . d3 ; scales ----
    float dA = 0.f, dB = 0.f;
    #pragma unroll
    for (int jh = 0; jh < 2; jh++) {
        float accd[4][4];
        #pragma unroll
        for (int j = 0; j < 4; j++)
            #pragma unroll
            for (int q = 0; q < 4; q++) accd[j][q] = 0.f;
        #pragma unroll
        for (int kk = 0; kk < 4; kk++)
            #pragma unroll
            for (int j = 0; j < 4; j++) {
                uint4 bb = g_MP[((jh * 4 + j) * 4 + kk) * 32 + lane];
                mma_bf16(accd[j], a2h[kk][0], a2h[kk][1], a2h[kk][2], a2h[kk][3], bb.x, bb.y);
                mma_bf16(accd[j], a2h[kk][0], a2h[kk][1], a2h[kk][2], a2h[kk][3], bb.z, bb.w);
                mma_bf16(accd[j], a2l[kk][0], a2l[kk][1], a2l[kk][2], a2l[kk][3], bb.x, bb.y);
            }
        #pragma unroll
        for (int j = 0; j < 4; j++) {
            int jj = jh * 4 + j;
            dA = fmaf(acc1[jj][0], accd[j][0], dA); dA = fmaf(acc1[jj][1], accd[j][1], dA);
            dB = fmaf(acc1[jj][2], accd[j][2], dB); dB = fmaf(acc1[jj][3], accd[j][3], dB);
        }
    }
    dA += __shfl_xor_sync(~0u, dA, 1); dA += __shfl_xor_sync(~0u, dA, 2);
    dB += __shfl_xor_sync(~0u, dB, 1); dB += __shfl_xor_sync(~0u, dB, 2);
    float oA = osq_s[16 * wg + g], oB = osq_s[16 * wg + g + 8];
    float scA = sqrtf(oA / fmaxf(oA - dA, oA * 1e-12f));
    float scB = sqrtf(oB / fmaxf(oB - dB, oB * 1e-12f));

    // STS WtP chunk 0
    #pragma unroll
    for (int q = 0; q < 8; q++) W2s[t + 256 * q] = wv[q];

    // ======== GEMM2 + fused epilogue: out = (H - b*Wt) * scale ========
    const size_t rowA = g0 + 16 * wg + g, rowB = rowA + 8;
    const float* hA = hs + rowA * FD;
    const float* hB = hs + rowB * FD;
    float* pA = out + rowA * FD;
    float* pB = out + rowB * FD;
    const bool fA = ((rowA & 4095) == 0);
    const bool fB = ((rowB & 4095) == 0);

    for (int nc = 0; nc < 8; nc++) {
        __syncthreads();
        const int buf = nc & 1;
        if (nc + 1 < 8) {
            #pragma unroll
            for (int q = 0; q < 8; q++) wv[q] = g_WP[(nc + 1) * 2048 + t + 256 * q];
        }
        // two halves of 8 n-tiles each -> only 32 accumulator regs live
        #pragma unroll
        for (int half = 0; half < 2; half++) {
            float acc2[8][4];
            #pragma unroll
            for (int jl = 0; jl < 8; jl++)
                #pragma unroll
                for (int q = 0; q < 4; q++) acc2[jl][q] = 0.f;
            #pragma unroll
            for (int kk = 0; kk < 4; kk++)
                #pragma unroll
                for (int jl = 0; jl < 8; jl++) {
                    uint4 bb = W2s[buf * 2048 + ((half * 8 + jl) * 4 + kk) * 32 + lane];
                    mma_bf16(acc2[jl], a2h[kk][0], a2h[kk][1], a2h[kk][2], a2h[kk][3], bb.x, bb.y);
                    mma_bf16(acc2[jl], a2h[kk][0], a2h[kk][1], a2h[kk][2], a2h[kk][3], bb.z, bb.w);
                    mma_bf16(acc2[jl], a2l[kk][0], a2l[kk][1], a2l[kk][2], a2l[kk][3], bb.x, bb.y);
                }
            #pragma unroll
            for (int jl = 0; jl < 8; jl++) {
                int col = nc * 128 + (half * 8 + jl) * 8 + 2 * tq;
                float2 h0 = *(const float2*)(hA + col);
                float2 h1 = *(const float2*)(hB + col);
                float2 o0, o1;
                o0.x = fA ? h0.x : (h0.x - acc2[jl][0]) * scA;
                o0.y = fA ? h0.y : (h0.y - acc2[jl][1]) * scA;
                o1.x = fB ? h1.x : (h1.x - acc2[jl][2]) * scB;
                o1.y = fB ? h1.y : (h1.y - acc2[jl][3]) * scB;
                __stcs((float2*)(pA + col), o0);
                __stcs((float2*)(pB + col), o1);
            }
        }
        if (nc + 1 < 8) {
            #pragma unroll
            for (int q = 0; q < 8; q++)
                W2s[((nc + 1) & 1) * 2048 + t + 256 * q] = wv[q];
        }
    }
}

extern "C" void kernel_launch(void* const* d_in, const int* in_sizes, int n_in,
                              void* d_out, int out_size) {
    const float* hs = (const float*)d_in[0];
    const float* probe = (const float*)d_in[1];
    float* out = (float*)d_out;

    k_zero<<<1, 256>>>();
    k_gram<<<8, 256>>>(probe);
    k_inv<<<1, 64>>>();
    k_w<<<256, 256>>>(probe);
    k_pack_p<<<64, 256>>>(probe);
    k_pack_w<<<64, 256>>>();
    k_pack_m<<<4, 256>>>();

    cudaFuncSetAttribute(k_main, cudaFuncAttributeMaxDynamicSharedMemorySize, SMEM_BYTES);
    int rows = in_sizes[0] / FD;            // 32768
    k_main<<<rows / MT, 256, SMEM_BYTES>>>(hs, out);
}

// round 7
// speedup vs baseline: 2.8403x; 1.1006x over previous
#include <cuda_runtime.h>
#include <cstdint>

#define FD 1024
#define RD 64
#define MT 128
#define NCH 16          // GEMM1 chunks of 64 cols

// ---------------- device scratch ----------------
__device__ float g_G[RD * RD];
__device__ float g_Minv[RD * RD];
__device__ float g_W[FD * RD];          // W = P * Minv, [f][r]
__device__ uint4 g_PP[64 * 8 * 32];     // GEMM1 B frags: [kstep][ntile][lane]
__device__ uint4 g_WP[128 * 4 * 32];    // GEMM2 B frags: [ntile][kstep][lane]
__device__ uint4 g_MP[8 * 4 * 32];      // d3 B frags (Minv)

// ---------------- helpers ----------------
__device__ __forceinline__ void split2(float x, float y, uint32_t& hi, uint32_t& lo) {
    asm("cvt.rn.bf16x2.f32 %0, %1, %2;" : "=r"(hi) : "f"(y), "f"(x));
    float xr = x - __uint_as_float(hi << 16);
    float yr = y - __uint_as_float(hi & 0xffff0000u);
    asm("cvt.rn.bf16x2.f32 %0, %1, %2;" : "=r"(lo) : "f"(yr), "f"(xr));
}

__device__ __forceinline__ void mma_bf16(float* d,
    uint32_t a0, uint32_t a1, uint32_t a2, uint32_t a3,
    uint32_t b0, uint32_t b1) {
    asm volatile("mma.sync.aligned.m16n8k16.row.col.f32.bf16.bf16.f32 "
        "{%0,%1,%2,%3}, {%4,%5,%6,%7}, {%8,%9}, {%0,%1,%2,%3};"
        : "+f"(d[0]), "+f"(d[1]), "+f"(d[2]), "+f"(d[3])
        : "r"(a0), "r"(a1), "r"(a2), "r"(a3), "r"(b0), "r"(b1));
}

__device__ __forceinline__ void cpa16(uint32_t s, const void* g) {
    asm volatile("cp.async.cg.shared.global [%0], [%1], 16;" :: "r"(s), "l"(g));
}
#define CP_COMMIT asm volatile("cp.async.commit_group;" ::: "memory")
#define CP_WAIT0  asm volatile("cp.async.wait_group 0;" ::: "memory")

// ---------------- prep kernels ----------------
__global__ void k_zero() {
    for (int i = threadIdx.x; i < RD * RD; i += 256) g_G[i] = 0.f;
}

// fused: gram (blocks 0-7) + pack_p (all 64 blocks)
__global__ void k_prep1(const float* __restrict__ probe) {
    __shared__ float Ps[128][68];
    int t = threadIdx.x;
    if (blockIdx.x < 8) {
        int c = blockIdx.x;
        #pragma unroll
        for (int i = 0; i < 8; i++) {
            int idx = t + 256 * i;
            int fl = idx >> 4, r4 = (idx & 15) << 2;
            float4 v = *(const float4*)(probe + (c * 128 + fl) * 64 + r4);
            *(float4*)(&Ps[fl][r4]) = v;
        }
        __syncthreads();
        int ti = (t >> 4) << 2, tj = (t & 15) << 2;
        float acc[4][4];
        #pragma unroll
        for (int a = 0; a < 4; a++)
            #pragma unroll
            for (int b = 0; b < 4; b++) acc[a][b] = 0.f;
        for (int k = 0; k < 128; k++) {
            float av[4], bv[4];
            #pragma unroll
            for (int a = 0; a < 4; a++) av[a] = Ps[k][ti + a];
            #pragma unroll
            for (int b = 0; b < 4; b++) bv[b] = Ps[k][tj + b];
            #pragma unroll
            for (int a = 0; a < 4; a++)
                #pragma unroll
                for (int b = 0; b < 4; b++) acc[a][b] = fmaf(av[a], bv[b], acc[a][b]);
        }
        #pragma unroll
        for (int a = 0; a < 4; a++)
            #pragma unroll
            for (int b = 0; b < 4; b++)
                atomicAdd(&g_G[(ti + a) * 64 + tj + b], acc[a][b]);
    }
    // pack_p (all blocks)
    {
        int id = blockIdx.x * 256 + t;
        int lane = id & 31, g = lane >> 2, tq = lane & 3;
        int kk = id >> 8, j = (id >> 5) & 7;
        int n = 8 * j + g, k0 = 16 * kk + 2 * tq;
        float p00 = probe[(k0) * 64 + n], p01 = probe[(k0 + 1) * 64 + n];
        float p10 = probe[(k0 + 8) * 64 + n], p11 = probe[(k0 + 9) * 64 + n];
        uint32_t h0, l0, h1, l1;
        split2(p00, p01, h0, l0);
        split2(p10, p11, h1, l1);
        g_PP[id] = make_uint4(h0, h1, l0, l1);
    }
}

__global__ void k_inv() {
    __shared__ float A[64][129];
    int r = threadIdx.x;
    for (int j = 0; j < 64; j++) A[r][j] = g_G[r * 64 + j];
    for (int j = 0; j < 64; j++) A[r][64 + j] = (r == j) ? 1.f : 0.f;
    __syncthreads();
    for (int k = 0; k < 64; k++) {
        if (r == k) {
            float inv = 1.f / A[k][k];
            for (int j = 0; j < 128; j++) A[k][j] *= inv;
        }
        __syncthreads();
        if (r != k) {
            float f = A[r][k];
            for (int j = 0; j < 128; j++) A[r][j] = fmaf(-f, A[k][j], A[r][j]);
        }
        __syncthreads();
    }
    for (int j = 0; j < 64; j++) g_Minv[r * 64 + j] = A[r][64 + j];
}

__global__ void k_w(const float* __restrict__ probe) {
    __shared__ float Ms[64 * 64];
    __shared__ float Ps[4][64];
    int t = threadIdx.x;
    for (int i = t; i < 4096; i += 256) Ms[i] = g_Minv[i];
    {
        int fl = t >> 6, k = t & 63;
        Ps[fl][k] = probe[(blockIdx.x * 4 + fl) * 64 + k];
    }
    __syncthreads();
    int fl = t >> 6, r = t & 63;
    float acc = 0.f;
    #pragma unroll 16
    for (int k = 0; k < 64; k++) acc = fmaf(Ps[fl][k], Ms[k * 64 + r], acc);
    g_W[(blockIdx.x * 4 + fl) * 64 + r] = acc;
}

// fused: pack_w (all 64 blocks) + pack_m (blocks 0-3)
__global__ void k_prep3() {
    int t = threadIdx.x;
    {
        int id = blockIdx.x * 256 + t;
        int lane = id & 31, g = lane >> 2, tq = lane & 3;
        int jj = id >> 7, kk = (id >> 5) & 3;
        int f = 8 * jj + g, r0 = 16 * kk + 2 * tq;
        float w00 = g_W[f * 64 + r0], w01 = g_W[f * 64 + r0 + 1];
        float w10 = g_W[f * 64 + r0 + 8], w11 = g_W[f * 64 + r0 + 9];
        uint32_t h0, l0, h1, l1;
        split2(w00, w01, h0, l0);
        split2(w10, w11, h1, l1);
        g_WP[id] = make_uint4(h0, h1, l0, l1);
    }
    if (blockIdx.x < 4) {
        int id = blockIdx.x * 256 + t;
        int lane = id & 31, g = lane >> 2, tq = lane & 3;
        int j = id >> 7, kk = (id >> 5) & 3;
        int n = 8 * j + g, k0 = 16 * kk + 2 * tq;
        float m00 = g_Minv[(k0) * 64 + n], m01 = g_Minv[(k0 + 1) * 64 + n];
        float m10 = g_Minv[(k0 + 8) * 64 + n], m11 = g_Minv[(k0 + 9) * 64 + n];
        uint32_t h0, l0, h1, l1;
        split2(m00, m01, h0, l0);
        split2(m10, m11, h1, l1);
        g_MP[id] = make_uint4(h0, h1, l0, l1);
    }
}

// ---------------- main kernel ----------------
// smem: GEMM1 B bufs = 2 x 1024 uint4 (32 KB); GEMM2 W bufs = 2 x 2048 uint4 (64 KB), same region
#define SMEM_WORDS 16448
#define SMEM_BYTES (SMEM_WORDS * 4)

__global__ void __launch_bounds__(256, 2)
k_main(const float* __restrict__ hs, float* __restrict__ out) {
    extern __shared__ uint32_t smw[];
    uint4* Bs = (uint4*)smw;

    const int t = threadIdx.x;
    const int wg = t >> 5, lane = t & 31, g = lane >> 2, tq = lane & 3;
    const size_t g0 = (size_t)blockIdx.x * MT;
    const size_t rowA = g0 + 16 * wg + g, rowB = rowA + 8;
    const float* hA = hs + rowA * FD;
    const float* hB = hs + rowB * FD;

    uint32_t sbase = (uint32_t)__cvta_generic_to_shared(smw);

    // prologue: stage GEMM1 B chunk 0 -> buf0
    #pragma unroll
    for (int q = 0; q < 4; q++)
        cpa16(sbase + (t + 256 * q) * 16, g_PP + t + 256 * q);
    CP_COMMIT;

    float acc1[8][4];
    #pragma unroll
    for (int j = 0; j < 8; j++)
        #pragma unroll
        for (int q = 0; q < 4; q++) acc1[j][q] = 0.f;
    float sqA = 0.f, sqB = 0.f;
    uint32_t ah[4][4], al[4][4];

    // ======== GEMM1: acc1 = H * P, K = 1024 ========
    for (int ch = 0; ch < NCH; ch++) {
        CP_WAIT0;
        __syncthreads();
        const int buf = ch & 1;
        if (ch + 1 < NCH) {
            const uint4* src = g_PP + (ch + 1) * 1024;
            #pragma unroll
            for (int q = 0; q < 4; q++)
                cpa16(sbase + (((buf ^ 1) * 1024 + t + 256 * q) * 16), src + t + 256 * q);
            CP_COMMIT;
        }
        const int cb = ch * 64 + 2 * tq;
        #pragma unroll
        for (int kk = 0; kk < 4; kk++) {
            int c0 = cb + 16 * kk;
            float2 fa0 = *(const float2*)(hA + c0);
            float2 fa1 = *(const float2*)(hA + c0 + 8);
            float2 fb0 = *(const float2*)(hB + c0);
            float2 fb1 = *(const float2*)(hB + c0 + 8);
            sqA = fmaf(fa0.x, fa0.x, fmaf(fa0.y, fa0.y, fmaf(fa1.x, fa1.x, fmaf(fa1.y, fa1.y, sqA))));
            sqB = fmaf(fb0.x, fb0.x, fmaf(fb0.y, fb0.y, fmaf(fb1.x, fb1.x, fmaf(fb1.y, fb1.y, sqB))));
            split2(fa0.x, fa0.y, ah[kk][0], al[kk][0]);
            split2(fb0.x, fb0.y, ah[kk][1], al[kk][1]);
            split2(fa1.x, fa1.y, ah[kk][2], al[kk][2]);
            split2(fb1.x, fb1.y, ah[kk][3], al[kk][3]);
        }
        #pragma unroll
        for (int kk = 0; kk < 4; kk++)
            #pragma unroll
            for (int j = 0; j < 8; j++) {
                uint4 bb = Bs[buf * 1024 + (kk * 8 + j) * 32 + lane];
                mma_bf16(acc1[j], ah[kk][0], ah[kk][1], ah[kk][2], ah[kk][3], bb.x, bb.y);
                mma_bf16(acc1[j], ah[kk][0], ah[kk][1], ah[kk][2], ah[kk][3], bb.z, bb.w);
                mma_bf16(acc1[j], al[kk][0], al[kk][1], al[kk][2], al[kk][3], bb.x, bb.y);
            }
    }

    // old-norm^2 per row (reduce over tq lanes)
    sqA += __shfl_xor_sync(~0u, sqA, 1); sqA += __shfl_xor_sync(~0u, sqA, 2);
    sqB += __shfl_xor_sync(~0u, sqB, 1); sqB += __shfl_xor_sync(~0u, sqB, 2);

    // all warps done reading GEMM1 Bs before W staging overwrites it
    __syncthreads();

    // prologue: stage GEMM2 W chunk 0 -> buf0 (2048 uint4)
    #pragma unroll
    for (int q = 0; q < 8; q++)
        cpa16(sbase + (t + 256 * q) * 16, g_WP + t + 256 * q);
    CP_COMMIT;

    // ---- repack acc1 (C frags) into GEMM2 A frags ----
    uint32_t a2h[4][4], a2l[4][4];
    #pragma unroll
    for (int kk = 0; kk < 4; kk++) {
        split2(acc1[2 * kk][0],     acc1[2 * kk][1],     a2h[kk][0], a2l[kk][0]);
        split2(acc1[2 * kk][2],     acc1[2 * kk][3],     a2h[kk][1], a2l[kk][1]);
        split2(acc1[2 * kk + 1][0], acc1[2 * kk + 1][1], a2h[kk][2], a2l[kk][2]);
        split2(acc1[2 * kk + 1][2], acc1[2 * kk + 1][3], a2h[kk][3], a2l[kk][3]);
    }

    // ---- d3 = b * Minv; dot = b . d3; scales ----
    float dA = 0.f, dB = 0.f;
    #pragma unroll
    for (int jh = 0; jh < 2; jh++) {
        float accd[4][4];
        #pragma unroll
        for (int j = 0; j < 4; j++)
            #pragma unroll
            for (int q = 0; q < 4; q++) accd[j][q] = 0.f;
        #pragma unroll
        for (int kk = 0; kk < 4; kk++)
            #pragma unroll
            for (int j = 0; j < 4; j++) {
                uint4 bb = g_MP[((jh * 4 + j) * 4 + kk) * 32 + lane];
                mma_bf16(accd[j], a2h[kk][0], a2h[kk][1], a2h[kk][2], a2h[kk][3], bb.x, bb.y);
                mma_bf16(accd[j], a2h[kk][0], a2h[kk][1], a2h[kk][2], a2h[kk][3], bb.z, bb.w);
                mma_bf16(accd[j], a2l[kk][0], a2l[kk][1], a2l[kk][2], a2l[kk][3], bb.x, bb.y);
            }
        #pragma unroll
        for (int j = 0; j < 4; j++) {
            int jj = jh * 4 + j;
            dA = fmaf(acc1[jj][0], accd[j][0], dA); dA = fmaf(acc1[jj][1], accd[j][1], dA);
            dB = fmaf(acc1[jj][2], accd[j][2], dB); dB = fmaf(acc1[jj][3], accd[j][3], dB);
        }
    }
    dA += __shfl_xor_sync(~0u, dA, 1); dA += __shfl_xor_sync(~0u, dA, 2);
    dB += __shfl_xor_sync(~0u, dB, 1); dB += __shfl_xor_sync(~0u, dB, 2);
    const float scA = sqrtf(sqA / fmaxf(sqA - dA, sqA * 1e-12f));
    const float scB = sqrtf(sqB / fmaxf(sqB - dB, sqB * 1e-12f));

    // ======== GEMM2 + fused epilogue: out = (H - b*Wt) * scale ========
    float* pA = out + rowA * FD;
    float* pB = out + rowB * FD;
    const bool fA = ((rowA & 4095) == 0);
    const bool fB = ((rowB & 4095) == 0);

    for (int nc = 0; nc < 8; nc++) {
        CP_WAIT0;
        __syncthreads();
        const int buf = nc & 1;
        if (nc + 1 < 8) {
            const uint4* src = g_WP + (nc + 1) * 2048;
            #pragma unroll
            for (int q = 0; q < 8; q++)
                cpa16(sbase + (((buf ^ 1) * 2048 + t + 256 * q) * 16), src + t + 256 * q);
            CP_COMMIT;
        }
        #pragma unroll
        for (int half = 0; half < 2; half++) {
            float acc2[8][4];
            #pragma unroll
            for (int jl = 0; jl < 8; jl++)
                #pragma unroll
                for (int q = 0; q < 4; q++) acc2[jl][q] = 0.f;
            #pragma unroll
            for (int kk = 0; kk < 4; kk++)
                #pragma unroll
                for (int jl = 0; jl < 8; jl++) {
                    uint4 bb = Bs[buf * 2048 + ((half * 8 + jl) * 4 + kk) * 32 + lane];
                    mma_bf16(acc2[jl], a2h[kk][0], a2h[kk][1], a2h[kk][2], a2h[kk][3], bb.x, bb.y);
                    mma_bf16(acc2[jl], a2h[kk][0], a2h[kk][1], a2h[kk][2], a2h[kk][3], bb.z, bb.w);
                    mma_bf16(acc2[jl], a2l[kk][0], a2l[kk][1], a2l[kk][2], a2l[kk][3], bb.x, bb.y);
                }
            #pragma unroll
            for (int jl = 0; jl < 8; jl++) {
                int col = nc * 128 + (half * 8 + jl) * 8 + 2 * tq;
                float2 h0 = *(const float2*)(hA + col);
                float2 h1 = *(const float2*)(hB + col);
                float2 o0, o1;
                o0.x = fA ? h0.x : (h0.x - acc2[jl][0]) * scA;
                o0.y = fA ? h0.y : (h0.y - acc2[jl][1]) * scA;
                o1.x = fB ? h1.x : (h1.x - acc2[jl][2]) * scB;
                o1.y = fB ? h1.y : (h1.y - acc2[jl][3]) * scB;
                __stcs((float2*)(pA + col), o0);
                __stcs((float2*)(pB + col), o1);
            }
        }
    }
}

extern "C" void kernel_launch(void* const* d_in, const int* in_sizes, int n_in,
                              void* d_out, int out_size) {
    const float* hs = (const float*)d_in[0];
    const float* probe = (const float*)d_in[1];
    float* out = (float*)d_out;

    k_zero<<<1, 256>>>();
    k_prep1<<<64, 256>>>(probe);
    k_inv<<<1, 64>>>();
    k_w<<<256, 256>>>(probe);
    k_prep3<<<64, 256>>>();

    cudaFuncSetAttribute(k_main, cudaFuncAttributeMaxDynamicSharedMemorySize, SMEM_BYTES);
    int rows = in_sizes[0] / FD;            // 32768
    k_main<<<rows / MT, 256, SMEM_BYTES>>>(hs, out);
}

// round 8
// speedup vs baseline: 3.0009x; 1.0566x over previous
#include <cuda_runtime.h>
#include <cstdint>

#define FD 1024
#define RD 64
#define MT 128
#define NCH 16          // GEMM1 chunks of 64 cols

// ---------------- device scratch ----------------
__device__ float g_G[RD * RD];
__device__ float g_Minv[RD * RD];
__device__ float g_W[FD * RD];          // W = P * Minv, [f][r]
__device__ uint4 g_PP[64 * 8 * 32];     // GEMM1 B frags: [kstep][ntile][lane] {h0,h1,l0,l1}
__device__ uint4 g_WP[128 * 4 * 32];    // GEMM2 B frags: [ntile][kstep][lane]
__device__ uint4 g_MP[8 * 4 * 32];      // d3 B frags (Minv)

// ---------------- helpers ----------------
__device__ __forceinline__ void split2(float x, float y, uint32_t& hi, uint32_t& lo) {
    asm("cvt.rn.bf16x2.f32 %0, %1, %2;" : "=r"(hi) : "f"(y), "f"(x));
    float xr = x - __uint_as_float(hi << 16);
    float yr = y - __uint_as_float(hi & 0xffff0000u);
    asm("cvt.rn.bf16x2.f32 %0, %1, %2;" : "=r"(lo) : "f"(yr), "f"(xr));
}
__device__ __forceinline__ uint32_t packbf(float x, float y) {
    uint32_t r;
    asm("cvt.rn.bf16x2.f32 %0, %1, %2;" : "=r"(r) : "f"(y), "f"(x));
    return r;
}

__device__ __forceinline__ void mma_bf16(float* d,
    uint32_t a0, uint32_t a1, uint32_t a2, uint32_t a3,
    uint32_t b0, uint32_t b1) {
    asm volatile("mma.sync.aligned.m16n8k16.row.col.f32.bf16.bf16.f32 "
        "{%0,%1,%2,%3}, {%4,%5,%6,%7}, {%8,%9}, {%0,%1,%2,%3};"
        : "+f"(d[0]), "+f"(d[1]), "+f"(d[2]), "+f"(d[3])
        : "r"(a0), "r"(a1), "r"(a2), "r"(a3), "r"(b0), "r"(b1));
}

__device__ __forceinline__ void cpa16(uint32_t s, const void* g) {
    asm volatile("cp.async.cg.shared.global [%0], [%1], 16;" :: "r"(s), "l"(g));
}
#define CP_COMMIT asm volatile("cp.async.commit_group;" ::: "memory")
#define CP_WAIT0  asm volatile("cp.async.wait_group 0;" ::: "memory")

// ---------------- prep kernels ----------------
__global__ void k_zero() {
    for (int i = threadIdx.x; i < RD * RD; i += 256) g_G[i] = 0.f;
}

// fused: gram (blocks 0-7) + pack_p (all 64 blocks)
__global__ void k_prep1(const float* __restrict__ probe) {
    __shared__ float Ps[128][68];
    int t = threadIdx.x;
    if (blockIdx.x < 8) {
        int c = blockIdx.x;
        #pragma unroll
        for (int i = 0; i < 8; i++) {
            int idx = t + 256 * i;
            int fl = idx >> 4, r4 = (idx & 15) << 2;
            float4 v = *(const float4*)(probe + (c * 128 + fl) * 64 + r4);
            *(float4*)(&Ps[fl][r4]) = v;
        }
        __syncthreads();
        int ti = (t >> 4) << 2, tj = (t & 15) << 2;
        float acc[4][4];
        #pragma unroll
        for (int a = 0; a < 4; a++)
            #pragma unroll
            for (int b = 0; b < 4; b++) acc[a][b] = 0.f;
        for (int k = 0; k < 128; k++) {
            float av[4], bv[4];
            #pragma unroll
            for (int a = 0; a < 4; a++) av[a] = Ps[k][ti + a];
            #pragma unroll
            for (int b = 0; b < 4; b++) bv[b] = Ps[k][tj + b];
            #pragma unroll
            for (int a = 0; a < 4; a++)
                #pragma unroll
                for (int b = 0; b < 4; b++) acc[a][b] = fmaf(av[a], bv[b], acc[a][b]);
        }
        #pragma unroll
        for (int a = 0; a < 4; a++)
            #pragma unroll
            for (int b = 0; b < 4; b++)
                atomicAdd(&g_G[(ti + a) * 64 + tj + b], acc[a][b]);
    }
    {
        int id = blockIdx.x * 256 + t;
        int lane = id & 31, g = lane >> 2, tq = lane & 3;
        int kk = id >> 8, j = (id >> 5) & 7;
        int n = 8 * j + g, k0 = 16 * kk + 2 * tq;
        float p00 = probe[(k0) * 64 + n], p01 = probe[(k0 + 1) * 64 + n];
        float p10 = probe[(k0 + 8) * 64 + n], p11 = probe[(k0 + 9) * 64 + n];
        uint32_t h0, l0, h1, l1;
        split2(p00, p01, h0, l0);
        split2(p10, p11, h1, l1);
        g_PP[id] = make_uint4(h0, h1, l0, l1);
    }
}

__global__ void k_inv() {
    __shared__ float A[64][129];
    int r = threadIdx.x;
    for (int j = 0; j < 64; j++) A[r][j] = g_G[r * 64 + j];
    for (int j = 0; j < 64; j++) A[r][64 + j] = (r == j) ? 1.f : 0.f;
    __syncthreads();
    for (int k = 0; k < 64; k++) {
        if (r == k) {
            float inv = 1.f / A[k][k];
            for (int j = 0; j < 128; j++) A[k][j] *= inv;
        }
        __syncthreads();
        if (r != k) {
            float f = A[r][k];
            for (int j = 0; j < 128; j++) A[r][j] = fmaf(-f, A[k][j], A[r][j]);
        }
        __syncthreads();
    }
    for (int j = 0; j < 64; j++) g_Minv[r * 64 + j] = A[r][64 + j];
}

__global__ void k_w(const float* __restrict__ probe) {
    __shared__ float Ms[64 * 64];
    __shared__ float Ps[4][64];
    int t = threadIdx.x;
    for (int i = t; i < 4096; i += 256) Ms[i] = g_Minv[i];
    {
        int fl = t >> 6, k = t & 63;
        Ps[fl][k] = probe[(blockIdx.x * 4 + fl) * 64 + k];
    }
    __syncthreads();
    int fl = t >> 6, r = t & 63;
    float acc = 0.f;
    #pragma unroll 16
    for (int k = 0; k < 64; k++) acc = fmaf(Ps[fl][k], Ms[k * 64 + r], acc);
    g_W[(blockIdx.x * 4 + fl) * 64 + r] = acc;
}

// fused: pack_w (all 64 blocks) + pack_m (blocks 0-3)
__global__ void k_prep3() {
    int t = threadIdx.x;
    {
        int id = blockIdx.x * 256 + t;
        int lane = id & 31, g = lane >> 2, tq = lane & 3;
        int jj = id >> 7, kk = (id >> 5) & 3;
        int f = 8 * jj + g, r0 = 16 * kk + 2 * tq;
        float w00 = g_W[f * 64 + r0], w01 = g_W[f * 64 + r0 + 1];
        float w10 = g_W[f * 64 + r0 + 8], w11 = g_W[f * 64 + r0 + 9];
        uint32_t h0, l0, h1, l1;
        split2(w00, w01, h0, l0);
        split2(w10, w11, h1, l1);
        g_WP[id] = make_uint4(h0, h1, l0, l1);
    }
    if (blockIdx.x < 4) {
        int id = blockIdx.x * 256 + t;
        int lane = id & 31, g = lane >> 2, tq = lane & 3;
        int j = id >> 7, kk = (id >> 5) & 3;
        int n = 8 * j + g, k0 = 16 * kk + 2 * tq;
        float m00 = g_Minv[(k0) * 64 + n], m01 = g_Minv[(k0 + 1) * 64 + n];
        float m10 = g_Minv[(k0 + 8) * 64 + n], m11 = g_Minv[(k0 + 9) * 64 + n];
        uint32_t h0, l0, h1, l1;
        split2(m00, m01, h0, l0);
        split2(m10, m11, h1, l1);
        g_MP[id] = make_uint4(h0, h1, l0, l1);
    }
}

// ---------------- main kernel ----------------
#define SMEM_WORDS 16448
#define SMEM_BYTES (SMEM_WORDS * 4)

__global__ void __launch_bounds__(256, 2)
k_main(const float* __restrict__ hs, float* __restrict__ out) {
    extern __shared__ uint32_t smw[];
    uint4* Bs = (uint4*)smw;

    const int t = threadIdx.x;
    const int wg = t >> 5, lane = t & 31, g = lane >> 2, tq = lane & 3;
    const size_t g0 = (size_t)blockIdx.x * MT;
    const size_t rowA = g0 + 16 * wg + g, rowB = rowA + 8;
    const float* hA = hs + rowA * FD;
    const float* hB = hs + rowB * FD;

    uint32_t sbase = (uint32_t)__cvta_generic_to_shared(smw);

    // prologue: stage GEMM1 B chunk 0 -> buf0
    #pragma unroll
    for (int q = 0; q < 4; q++)
        cpa16(sbase + (t + 256 * q) * 16, g_PP + t + 256 * q);
    CP_COMMIT;

    float acc1[8][4];
    #pragma unroll
    for (int j = 0; j < 8; j++)
        #pragma unroll
        for (int q = 0; q < 4; q++) acc1[j][q] = 0.f;
    float sqA = 0.f, sqB = 0.f;

    // prefetch H chunk 0 (16 float2: [kk][fa0,fa1,fb0,fb1])
    float2 pf[16];
    {
        const int cb = 2 * tq;
        #pragma unroll
        for (int kk = 0; kk < 4; kk++) {
            int c0 = cb + 16 * kk;
            pf[4 * kk + 0] = *(const float2*)(hA + c0);
            pf[4 * kk + 1] = *(const float2*)(hA + c0 + 8);
            pf[4 * kk + 2] = *(const float2*)(hB + c0);
            pf[4 * kk + 3] = *(const float2*)(hB + c0 + 8);
        }
    }

    // ======== GEMM1: acc1 = H * P, K = 1024 (2-term: Ah*(Bh+Bl)) ========
    for (int ch = 0; ch < NCH; ch++) {
        CP_WAIT0;
        __syncthreads();
        const int buf = ch & 1;
        if (ch + 1 < NCH) {
            const uint4* src = g_PP + (ch + 1) * 1024;
            #pragma unroll
            for (int q = 0; q < 4; q++)
                cpa16(sbase + (((buf ^ 1) * 1024 + t + 256 * q) * 16), src + t + 256 * q);
            CP_COMMIT;
        }
        // convert prefetched H -> A frags, accumulate norms
        uint32_t ah[4][4];
        #pragma unroll
        for (int kk = 0; kk < 4; kk++) {
            float2 fa0 = pf[4 * kk + 0], fa1 = pf[4 * kk + 1];
            float2 fb0 = pf[4 * kk + 2], fb1 = pf[4 * kk + 3];
            sqA = fmaf(fa0.x, fa0.x, fmaf(fa0.y, fa0.y, fmaf(fa1.x, fa1.x, fmaf(fa1.y, fa1.y, sqA))));
            sqB = fmaf(fb0.x, fb0.x, fmaf(fb0.y, fb0.y, fmaf(fb1.x, fb1.x, fmaf(fb1.y, fb1.y, sqB))));
            ah[kk][0] = packbf(fa0.x, fa0.y);
            ah[kk][1] = packbf(fb0.x, fb0.y);
            ah[kk][2] = packbf(fa1.x, fa1.y);
            ah[kk][3] = packbf(fb1.x, fb1.y);
        }
        // prefetch next chunk's H (rides under the mma below)
        if (ch + 1 < NCH) {
            const int cb = (ch + 1) * 64 + 2 * tq;
            #pragma unroll
            for (int kk = 0; kk < 4; kk++) {
                int c0 = cb + 16 * kk;
                pf[4 * kk + 0] = *(const float2*)(hA + c0);
                pf[4 * kk + 1] = *(const float2*)(hA + c0 + 8);
                pf[4 * kk + 2] = *(const float2*)(hB + c0);
                pf[4 * kk + 3] = *(const float2*)(hB + c0 + 8);
            }
        }
        #pragma unroll
        for (int kk = 0; kk < 4; kk++)
            #pragma unroll
            for (int j = 0; j < 8; j++) {
                uint4 bb = Bs[buf * 1024 + (kk * 8 + j) * 32 + lane];
                mma_bf16(acc1[j], ah[kk][0], ah[kk][1], ah[kk][2], ah[kk][3], bb.x, bb.y);
                mma_bf16(acc1[j], ah[kk][0], ah[kk][1], ah[kk][2], ah[kk][3], bb.z, bb.w);
            }
    }

    // old-norm^2 per row (reduce over tq lanes)
    sqA += __shfl_xor_sync(~0u, sqA, 1); sqA += __shfl_xor_sync(~0u, sqA, 2);
    sqB += __shfl_xor_sync(~0u, sqB, 1); sqB += __shfl_xor_sync(~0u, sqB, 2);

    __syncthreads();   // all warps done with GEMM1 Bs

    // prologue: stage GEMM2 W chunk 0 -> buf0 (2048 uint4)
    #pragma unroll
    for (int q = 0; q < 8; q++)
        cpa16(sbase + (t + 256 * q) * 16, g_WP + t + 256 * q);
    CP_COMMIT;

    // ---- repack acc1 (C frags) into GEMM2 A frags (hi only) ----
    uint32_t a2h[4][4];
    #pragma unroll
    for (int kk = 0; kk < 4; kk++) {
        a2h[kk][0] = packbf(acc1[2 * kk][0],     acc1[2 * kk][1]);
        a2h[kk][1] = packbf(acc1[2 * kk][2],     acc1[2 * kk][3]);
        a2h[kk][2] = packbf(acc1[2 * kk + 1][0], acc1[2 * kk + 1][1]);
        a2h[kk][3] = packbf(acc1[2 * kk + 1][2], acc1[2 * kk + 1][3]);
    }

    // ---- d3 = b * Minv; dot = b . d3; scales ----
    float dA = 0.f, dB = 0.f;
    #pragma unroll
    for (int jh = 0; jh < 2; jh++) {
        float accd[4][4];
        #pragma unroll
        for (int j = 0; j < 4; j++)
            #pragma unroll
            for (int q = 0; q < 4; q++) accd[j][q] = 0.f;
        #pragma unroll
        for (int kk = 0; kk < 4; kk++)
            #pragma unroll
            for (int j = 0; j < 4; j++) {
                uint4 bb = g_MP[((jh * 4 + j) * 4 + kk) * 32 + lane];
                mma_bf16(accd[j], a2h[kk][0], a2h[kk][1], a2h[kk][2], a2h[kk][3], bb.x, bb.y);
                mma_bf16(accd[j], a2h[kk][0], a2h[kk][1], a2h[kk][2], a2h[kk][3], bb.z, bb.w);
            }
        #pragma unroll
        for (int j = 0; j < 4; j++) {
            int jj = jh * 4 + j;
            dA = fmaf(acc1[jj][0], accd[j][0], dA); dA = fmaf(acc1[jj][1], accd[j][1], dA);
            dB = fmaf(acc1[jj][2], accd[j][2], dB); dB = fmaf(acc1[jj][3], accd[j][3], dB);
        }
    }
    dA += __shfl_xor_sync(~0u, dA, 1); dA += __shfl_xor_sync(~0u, dA, 2);
    dB += __shfl_xor_sync(~0u, dB, 1); dB += __shfl_xor_sync(~0u, dB, 2);
    const float scA = sqrtf(sqA / fmaxf(sqA - dA, sqA * 1e-12f));
    const float scB = sqrtf(sqB / fmaxf(sqB - dB, sqB * 1e-12f));

    // ======== GEMM2 + fused epilogue: out = (H - b*Wt) * scale ========
    float* pA = out + rowA * FD;
    float* pB = out + rowB * FD;
    const bool fA = ((rowA & 4095) == 0);
    const bool fB = ((rowB & 4095) == 0);

    for (int nc = 0; nc < 8; nc++) {
        CP_WAIT0;
        __syncthreads();
        const int buf = nc & 1;
        if (nc + 1 < 8) {
            const uint4* src = g_WP + (nc + 1) * 2048;
            #pragma unroll
            for (int q = 0; q < 8; q++)
                cpa16(sbase + (((buf ^ 1) * 2048 + t + 256 * q) * 16), src + t + 256 * q);
            CP_COMMIT;
        }
        #pragma unroll
        for (int half = 0; half < 2; half++) {
            // hoist H re-reads above the mma so latency hides under tensor work
            float2 h0[8], h1[8];
            #pragma unroll
            for (int jl = 0; jl < 8; jl++) {
                int col = nc * 128 + (half * 8 + jl) * 8 + 2 * tq;
                h0[jl] = *(const float2*)(hA + col);
                h1[jl] = *(const float2*)(hB + col);
            }
            float acc2[8][4];
            #pragma unroll
            for (int jl = 0; jl < 8; jl++)
                #pragma unroll
                for (int q = 0; q < 4; q++) acc2[jl][q] = 0.f;
            #pragma unroll
            for (int kk = 0; kk < 4; kk++)
                #pragma unroll
                for (int jl = 0; jl < 8; jl++) {
                    uint4 bb = Bs[buf * 2048 + ((half * 8 + jl) * 4 + kk) * 32 + lane];
                    mma_bf16(acc2[jl], a2h[kk][0], a2h[kk][1], a2h[kk][2], a2h[kk][3], bb.x, bb.y);
                    mma_bf16(acc2[jl], a2h[kk][0], a2h[kk][1], a2h[kk][2], a2h[kk][3], bb.z, bb.w);
                }
            #pragma unroll
            for (int jl = 0; jl < 8; jl++) {
                int col = nc * 128 + (half * 8 + jl) * 8 + 2 * tq;
                float2 o0, o1;
                o0.x = fA ? h0[jl].x : (h0[jl].x - acc2[jl][0]) * scA;
                o0.y = fA ? h0[jl].y : (h0[jl].y - acc2[jl][1]) * scA;
                o1.x = fB ? h1[jl].x : (h1[jl].x - acc2[jl][2]) * scB;
                o1.y = fB ? h1[jl].y : (h1[jl].y - acc2[jl][3]) * scB;
                __stcs((float2*)(pA + col), o0);
                __stcs((float2*)(pB + col), o1);
            }
        }
    }
}

extern "C" void kernel_launch(void* const* d_in, const int* in_sizes, int n_in,
                              void* d_out, int out_size) {
    const float* hs = (const float*)d_in[0];
    const float* probe = (const float*)d_in[1];
    float* out = (float*)d_out;

    k_zero<<<1, 256>>>();
    k_prep1<<<64, 256>>>(probe);
    k_inv<<<1, 64>>>();
    k_w<<<256, 256>>>(probe);
    k_prep3<<<64, 256>>>();

    cudaFuncSetAttribute(k_main, cudaFuncAttributeMaxDynamicSharedMemorySize, SMEM_BYTES);
    int rows = in_sizes[0] / FD;            // 32768
    k_main<<<rows / MT, 256, SMEM_BYTES>>>(hs, out);
}